// round 1
// baseline (speedup 1.0000x reference)
#include <cuda_runtime.h>
#include <math.h>

#define B_  32
#define L_  64
#define D_  768
#define LL_ (L_*L_)     // 4096
#define OUTD_ (2*D_)    // 1536

// scratch: pooled vectors (B, D)
__device__ float g_pooled[B_ * D_];

// ---------------------------------------------------------------------------
// Stage A: per-batch fused  t-dots -> masked softmax marginals -> pooled
// grid = B_, block = 256
// ---------------------------------------------------------------------------
__global__ __launch_bounds__(256) void stageA(
    const float* __restrict__ a1, const float* __restrict__ a2,
    const int*   __restrict__ m1, const int*   __restrict__ m2,
    const float* __restrict__ we_w)
{
    __shared__ float sw[D_];
    __shared__ float t1[L_], t2[L_];
    __shared__ float rowc[L_], colc[L_];
    __shared__ float red[8];
    __shared__ int   sl1, sl2;
    __shared__ float smax, sdenom;

    const int b    = blockIdx.x;
    const int tid  = threadIdx.x;
    const int lane = tid & 31;
    const int wid  = tid >> 5;

    // load we_w into smem
    for (int i = tid; i < D_; i += 256) sw[i] = we_w[i];

    // l1, l2 (warp 0 / warp 1)
    if (wid == 0) {
        int s = m1[b*L_ + lane] + m1[b*L_ + lane + 32];
        #pragma unroll
        for (int o = 16; o; o >>= 1) s += __shfl_xor_sync(0xffffffffu, s, o);
        if (lane == 0) sl1 = s - 2;
    } else if (wid == 1) {
        int s = m2[b*L_ + lane] + m2[b*L_ + lane + 32];
        #pragma unroll
        for (int o = 16; o; o >>= 1) s += __shfl_xor_sync(0xffffffffu, s, o);
        if (lane == 0) sl2 = s - 2;
    }
    __syncthreads();

    const float*  base1  = a1 + (size_t)b * L_ * D_;
    const float*  base2  = a2 + (size_t)b * L_ * D_;
    const float4* base1v = (const float4*)base1;
    const float4* base2v = (const float4*)base2;
    const float4* swv    = (const float4*)sw;

    // t1[r] = dot(a1[b,r], w), t2[r] = dot(a2[b,r], w). 128 row-tasks over 8 warps.
    for (int task = wid; task < 2*L_; task += 8) {
        const float4* row = (task < L_) ? (base1v + task*(D_/4))
                                        : (base2v + (task - L_)*(D_/4));
        float s = 0.f;
        #pragma unroll
        for (int k = 0; k < 6; k++) {
            float4 v = row[lane + 32*k];
            float4 w = swv[lane + 32*k];
            s += v.x*w.x + v.y*w.y + v.z*w.z + v.w*w.w;
        }
        #pragma unroll
        for (int o = 16; o; o >>= 1) s += __shfl_xor_sync(0xffffffffu, s, o);
        if (lane == 0) { if (task < L_) t1[task] = s; else t2[task - L_] = s; }
    }
    __syncthreads();

    const int l1 = sl1, l2 = sl2;
    const int nvalid = l1 * l2;

    // pass 1: max over all 4096 masked logits
    float lmax = -1e30f;
    for (int kk = tid; kk < LL_; kk += 256) {
        float we = 0.f;
        if (kk < nvalid) {
            int i = kk / l2;
            int j = kk - i*l2;
            we = t1[i+1] - t2[j+1];
        }
        float m = (fabsf(we) < 1e-7f) ? -1e7f : we;
        lmax = fmaxf(lmax, m);
    }
    #pragma unroll
    for (int o = 16; o; o >>= 1) lmax = fmaxf(lmax, __shfl_xor_sync(0xffffffffu, lmax, o));
    if (lane == 0) red[wid] = lmax;
    __syncthreads();
    if (tid == 0) {
        float m = red[0];
        #pragma unroll
        for (int i = 1; i < 8; i++) m = fmaxf(m, red[i]);
        smax = m;
    }
    __syncthreads();
    const float mx = smax;

    // pass 2: denominator
    float lsum = 0.f;
    for (int kk = tid; kk < LL_; kk += 256) {
        float we = 0.f;
        if (kk < nvalid) {
            int i = kk / l2;
            int j = kk - i*l2;
            we = t1[i+1] - t2[j+1];
        }
        float m = (fabsf(we) < 1e-7f) ? -1e7f : we;
        lsum += __expf(m - mx);
    }
    #pragma unroll
    for (int o = 16; o; o >>= 1) lsum += __shfl_xor_sync(0xffffffffu, lsum, o);
    if (lane == 0) red[wid] = lsum;
    __syncthreads();
    if (tid == 0) {
        float s = 0.f;
        #pragma unroll
        for (int i = 0; i < 8; i++) s += red[i];
        sdenom = s;
    }
    __syncthreads();
    const float denom = sdenom;

    // pass 3: softmax marginals (row sums over j, col sums over i) — deterministic
    if (tid < L_) {
        const int i = tid;
        float s = 0.f;
        if (i < l1) {
            const float ti = t1[i+1];
            for (int j = 0; j < l2; j++) {
                float we = ti - t2[j+1];
                float m = (fabsf(we) < 1e-7f) ? -1e7f : we;
                s += __expf(m - mx);
            }
        }
        rowc[i] = s / denom;
    } else if (tid < 2*L_) {
        const int j = tid - L_;
        float s = 0.f;
        if (j < l2) {
            const float tj = t2[j+1];
            for (int i = 0; i < l1; i++) {
                float we = t1[i+1] - tj;
                float m = (fabsf(we) < 1e-7f) ? -1e7f : we;
                s += __expf(m - mx);
            }
        }
        colc[j] = s / denom;
    }
    __syncthreads();

    // pass 4: pooled[b,d] = sum_i rowc[i]*a1[b,i+1,d] - sum_j colc[j]*a2[b,j+1,d]
    float4* poolv = (float4*)g_pooled;
    for (int c = tid; c < D_/4; c += 256) {   // 192 float4 columns
        float4 acc = make_float4(0.f, 0.f, 0.f, 0.f);
        for (int i = 0; i < l1; i++) {
            float r = rowc[i];
            float4 v = base1v[(i+1)*(D_/4) + c];
            acc.x += r*v.x; acc.y += r*v.y; acc.z += r*v.z; acc.w += r*v.w;
        }
        for (int j = 0; j < l2; j++) {
            float cc = colc[j];
            float4 v = base2v[(j+1)*(D_/4) + c];
            acc.x -= cc*v.x; acc.y -= cc*v.y; acc.z -= cc*v.z; acc.w -= cc*v.w;
        }
        poolv[b*(D_/4) + c] = acc;
    }
}

// ---------------------------------------------------------------------------
// Stage B: out[b,o] = tanh( dot(pooled[b], fc_w[o]) + fc_b[o] )
// grid = 48 (32 output rows each), block = 256 (8 warps; warp owns 4 batches)
// fc_w streamed from DRAM once per row; pooled held in registers (4 batches/warp).
// ---------------------------------------------------------------------------
__global__ __launch_bounds__(256) void stageB(
    const float* __restrict__ fc_w, const float* __restrict__ fc_b,
    float* __restrict__ out)
{
    const int lane = threadIdx.x & 31;
    const int wid  = threadIdx.x >> 5;
    const int o0   = blockIdx.x * 32;
    const int b0   = wid * 4;

    const float4* poolv = (const float4*)g_pooled;

    // preload pooled for 4 batches: lane owns float4 columns lane + 32k, k<6
    float4 p[4][6];
    #pragma unroll
    for (int bb = 0; bb < 4; bb++)
        #pragma unroll
        for (int k = 0; k < 6; k++)
            p[bb][k] = poolv[(b0 + bb)*(D_/4) + lane + 32*k];

    for (int r = 0; r < 32; r++) {
        const int o = o0 + r;
        const float4* wrow = (const float4*)(fc_w + (size_t)o * D_);
        float4 w[6];
        #pragma unroll
        for (int k = 0; k < 6; k++) w[k] = wrow[lane + 32*k];

        float a0 = 0.f, a1 = 0.f, a2 = 0.f, a3 = 0.f;
        #pragma unroll
        for (int k = 0; k < 6; k++) {
            a0 += w[k].x*p[0][k].x + w[k].y*p[0][k].y + w[k].z*p[0][k].z + w[k].w*p[0][k].w;
            a1 += w[k].x*p[1][k].x + w[k].y*p[1][k].y + w[k].z*p[1][k].z + w[k].w*p[1][k].w;
            a2 += w[k].x*p[2][k].x + w[k].y*p[2][k].y + w[k].z*p[2][k].z + w[k].w*p[2][k].w;
            a3 += w[k].x*p[3][k].x + w[k].y*p[3][k].y + w[k].z*p[3][k].z + w[k].w*p[3][k].w;
        }
        #pragma unroll
        for (int off = 16; off; off >>= 1) {
            a0 += __shfl_xor_sync(0xffffffffu, a0, off);
            a1 += __shfl_xor_sync(0xffffffffu, a1, off);
            a2 += __shfl_xor_sync(0xffffffffu, a2, off);
            a3 += __shfl_xor_sync(0xffffffffu, a3, off);
        }
        if (lane == 0) {
            const float bias = fc_b[o];
            out[(size_t)(b0+0)*OUTD_ + o] = tanhf(a0 + bias);
            out[(size_t)(b0+1)*OUTD_ + o] = tanhf(a1 + bias);
            out[(size_t)(b0+2)*OUTD_ + o] = tanhf(a2 + bias);
            out[(size_t)(b0+3)*OUTD_ + o] = tanhf(a3 + bias);
        }
    }
}

extern "C" void kernel_launch(void* const* d_in, const int* in_sizes, int n_in,
                              void* d_out, int out_size)
{
    const float* a1   = (const float*)d_in[0];  // (B, L, D)
    const float* a2   = (const float*)d_in[1];  // (B, L, D)
    const int*   m1   = (const int*)  d_in[2];  // (B, L)
    const int*   m2   = (const int*)  d_in[3];  // (B, L)
    const float* we_w = (const float*)d_in[4];  // (1, D)
    const float* fc_w = (const float*)d_in[5];  // (2D, D)
    const float* fc_b = (const float*)d_in[6];  // (2D,)
    float* out = (float*)d_out;                 // (B, 2D)

    stageA<<<B_, 256>>>(a1, a2, m1, m2, we_w);
    stageB<<<48, 256>>>(fc_w, fc_b, out);
}

// round 2
// speedup vs baseline: 1.0425x; 1.0425x over previous
#include <cuda_runtime.h>
#include <math.h>

#define B_  32
#define L_  64
#define D_  768
#define LL_ (L_*L_)     // 4096
#define OUTD_ (2*D_)    // 1536

#define ROWS_PER_BLK 12     // 128 blocks * 12 = 1536 output rows

// scratch: pooled vectors (B, D)
__device__ float g_pooled[B_ * D_];

// ---------------------------------------------------------------------------
// Stage A: per-batch fused  t-dots -> masked softmax marginals -> pooled
// grid = B_, block = 256
// ---------------------------------------------------------------------------
__global__ __launch_bounds__(256) void stageA(
    const float* __restrict__ a1, const float* __restrict__ a2,
    const int*   __restrict__ m1, const int*   __restrict__ m2,
    const float* __restrict__ we_w)
{
    __shared__ float sw[D_];
    __shared__ float t1[L_], t2[L_];
    __shared__ float rowc[L_], colc[L_];
    __shared__ float red[8];
    __shared__ int   sl1, sl2;
    __shared__ float smax, sdenom;

    const int b    = blockIdx.x;
    const int tid  = threadIdx.x;
    const int lane = tid & 31;
    const int wid  = tid >> 5;

    for (int i = tid; i < D_; i += 256) sw[i] = we_w[i];

    if (wid == 0) {
        int s = m1[b*L_ + lane] + m1[b*L_ + lane + 32];
        #pragma unroll
        for (int o = 16; o; o >>= 1) s += __shfl_xor_sync(0xffffffffu, s, o);
        if (lane == 0) sl1 = s - 2;
    } else if (wid == 1) {
        int s = m2[b*L_ + lane] + m2[b*L_ + lane + 32];
        #pragma unroll
        for (int o = 16; o; o >>= 1) s += __shfl_xor_sync(0xffffffffu, s, o);
        if (lane == 0) sl2 = s - 2;
    }
    __syncthreads();

    const float4* base1v = (const float4*)(a1 + (size_t)b * L_ * D_);
    const float4* base2v = (const float4*)(a2 + (size_t)b * L_ * D_);
    const float4* swv    = (const float4*)sw;

    // t1[r] = dot(a1[b,r], w), t2[r] = dot(a2[b,r], w). 128 row-tasks / 8 warps.
    for (int task = wid; task < 2*L_; task += 8) {
        const float4* row = (task < L_) ? (base1v + task*(D_/4))
                                        : (base2v + (task - L_)*(D_/4));
        float s = 0.f;
        #pragma unroll
        for (int k = 0; k < 6; k++) {
            float4 v = row[lane + 32*k];
            float4 w = swv[lane + 32*k];
            s += v.x*w.x + v.y*w.y + v.z*w.z + v.w*w.w;
        }
        #pragma unroll
        for (int o = 16; o; o >>= 1) s += __shfl_xor_sync(0xffffffffu, s, o);
        if (lane == 0) { if (task < L_) t1[task] = s; else t2[task - L_] = s; }
    }
    __syncthreads();

    const int l1 = sl1, l2 = sl2;
    const int nvalid = l1 * l2;

    // pass 1: max over masked logits
    float lmax = -1e30f;
    for (int kk = tid; kk < LL_; kk += 256) {
        float we = 0.f;
        if (kk < nvalid) {
            int i = kk / l2;
            int j = kk - i*l2;
            we = t1[i+1] - t2[j+1];
        }
        float m = (fabsf(we) < 1e-7f) ? -1e7f : we;
        lmax = fmaxf(lmax, m);
    }
    #pragma unroll
    for (int o = 16; o; o >>= 1) lmax = fmaxf(lmax, __shfl_xor_sync(0xffffffffu, lmax, o));
    if (lane == 0) red[wid] = lmax;
    __syncthreads();
    if (tid == 0) {
        float m = red[0];
        #pragma unroll
        for (int i = 1; i < 8; i++) m = fmaxf(m, red[i]);
        smax = m;
    }
    __syncthreads();
    const float mx = smax;

    // pass 2: denominator
    float lsum = 0.f;
    for (int kk = tid; kk < LL_; kk += 256) {
        float we = 0.f;
        if (kk < nvalid) {
            int i = kk / l2;
            int j = kk - i*l2;
            we = t1[i+1] - t2[j+1];
        }
        float m = (fabsf(we) < 1e-7f) ? -1e7f : we;
        lsum += __expf(m - mx);
    }
    #pragma unroll
    for (int o = 16; o; o >>= 1) lsum += __shfl_xor_sync(0xffffffffu, lsum, o);
    if (lane == 0) red[wid] = lsum;
    __syncthreads();
    if (tid == 0) {
        float s = 0.f;
        #pragma unroll
        for (int i = 0; i < 8; i++) s += red[i];
        sdenom = s;
    }
    __syncthreads();
    const float denom = sdenom;

    // pass 3: softmax marginals
    if (tid < L_) {
        const int i = tid;
        float s = 0.f;
        if (i < l1) {
            const float ti = t1[i+1];
            for (int j = 0; j < l2; j++) {
                float we = ti - t2[j+1];
                float m = (fabsf(we) < 1e-7f) ? -1e7f : we;
                s += __expf(m - mx);
            }
        }
        rowc[i] = s / denom;
    } else if (tid < 2*L_) {
        const int j = tid - L_;
        float s = 0.f;
        if (j < l2) {
            const float tj = t2[j+1];
            for (int i = 0; i < l1; i++) {
                float we = t1[i+1] - tj;
                float m = (fabsf(we) < 1e-7f) ? -1e7f : we;
                s += __expf(m - mx);
            }
        }
        colc[j] = s / denom;
    }
    __syncthreads();

    // pass 4: pooled
    float4* poolv = (float4*)g_pooled;
    for (int c = tid; c < D_/4; c += 256) {
        float4 acc = make_float4(0.f, 0.f, 0.f, 0.f);
        for (int i = 0; i < l1; i++) {
            float r = rowc[i];
            float4 v = base1v[(i+1)*(D_/4) + c];
            acc.x += r*v.x; acc.y += r*v.y; acc.z += r*v.z; acc.w += r*v.w;
        }
        for (int j = 0; j < l2; j++) {
            float cc = colc[j];
            float4 v = base2v[(j+1)*(D_/4) + c];
            acc.x -= cc*v.x; acc.y -= cc*v.y; acc.z -= cc*v.z; acc.w -= cc*v.w;
        }
        poolv[b*(D_/4) + c] = acc;
    }
}

// ---------------------------------------------------------------------------
// Stage B v2: out[b,o] = tanh( dot(pooled[b], fc_w[o]) + fc_b[o] )
// grid = 128 blocks x 256 threads. Each block: 12 output rows, all 32 batches.
// fc_w tile (12x768 = 36KB) staged into smem with 9 independent float4 LDGs
// per thread (latency amortized chip-wide). Each warp holds pooled for 4
// batches in registers and sweeps the 12 rows from smem.
// ---------------------------------------------------------------------------
__global__ __launch_bounds__(256) void stageB(
    const float* __restrict__ fc_w, const float* __restrict__ fc_b,
    float* __restrict__ out)
{
    __shared__ float sA[ROWS_PER_BLK * D_];   // 36 KB

    const int tid  = threadIdx.x;
    const int lane = tid & 31;
    const int wid  = tid >> 5;
    const int o0   = blockIdx.x * ROWS_PER_BLK;
    const int b0   = wid * 4;                 // 8 warps x 4 batches = 32

    // stage fc_w tile: 12*768/4 = 2304 float4, 9 per thread, all independent
    {
        const float4* src = (const float4*)(fc_w + (size_t)o0 * D_);
        float4*       dst = (float4*)sA;
        #pragma unroll
        for (int k = 0; k < (ROWS_PER_BLK * D_ / 4) / 256; k++)
            dst[tid + 256*k] = src[tid + 256*k];
    }

    // preload pooled for 4 batches (overlaps with staging latency)
    const float4* poolv = (const float4*)g_pooled;
    float4 p[4][6];
    #pragma unroll
    for (int bb = 0; bb < 4; bb++)
        #pragma unroll
        for (int k = 0; k < 6; k++)
            p[bb][k] = poolv[(b0 + bb)*(D_/4) + lane + 32*k];

    __syncthreads();

    const float4* sAv = (const float4*)sA;

    #pragma unroll
    for (int r = 0; r < ROWS_PER_BLK; r++) {
        const int o = o0 + r;
        float4 w[6];
        #pragma unroll
        for (int k = 0; k < 6; k++) w[k] = sAv[r*(D_/4) + lane + 32*k];

        float a0 = 0.f, a1 = 0.f, a2 = 0.f, a3 = 0.f;
        #pragma unroll
        for (int k = 0; k < 6; k++) {
            a0 += w[k].x*p[0][k].x + w[k].y*p[0][k].y + w[k].z*p[0][k].z + w[k].w*p[0][k].w;
            a1 += w[k].x*p[1][k].x + w[k].y*p[1][k].y + w[k].z*p[1][k].z + w[k].w*p[1][k].w;
            a2 += w[k].x*p[2][k].x + w[k].y*p[2][k].y + w[k].z*p[2][k].z + w[k].w*p[2][k].w;
            a3 += w[k].x*p[3][k].x + w[k].y*p[3][k].y + w[k].z*p[3][k].z + w[k].w*p[3][k].w;
        }
        #pragma unroll
        for (int off = 16; off; off >>= 1) {
            a0 += __shfl_xor_sync(0xffffffffu, a0, off);
            a1 += __shfl_xor_sync(0xffffffffu, a1, off);
            a2 += __shfl_xor_sync(0xffffffffu, a2, off);
            a3 += __shfl_xor_sync(0xffffffffu, a3, off);
        }
        if (lane == 0) {
            const float bias = fc_b[o];
            out[(size_t)(b0+0)*OUTD_ + o] = tanhf(a0 + bias);
            out[(size_t)(b0+1)*OUTD_ + o] = tanhf(a1 + bias);
            out[(size_t)(b0+2)*OUTD_ + o] = tanhf(a2 + bias);
            out[(size_t)(b0+3)*OUTD_ + o] = tanhf(a3 + bias);
        }
    }
}

extern "C" void kernel_launch(void* const* d_in, const int* in_sizes, int n_in,
                              void* d_out, int out_size)
{
    const float* a1   = (const float*)d_in[0];  // (B, L, D)
    const float* a2   = (const float*)d_in[1];  // (B, L, D)
    const int*   m1   = (const int*)  d_in[2];  // (B, L)
    const int*   m2   = (const int*)  d_in[3];  // (B, L)
    const float* we_w = (const float*)d_in[4];  // (1, D)
    const float* fc_w = (const float*)d_in[5];  // (2D, D)
    const float* fc_b = (const float*)d_in[6];  // (2D,)
    float* out = (float*)d_out;                 // (B, 2D)

    stageA<<<B_, 256>>>(a1, a2, m1, m2, we_w);
    stageB<<<OUTD_ / ROWS_PER_BLK, 256>>>(fc_w, fc_b, out);
}

// round 3
// speedup vs baseline: 1.3465x; 1.2916x over previous
#include <cuda_runtime.h>
#include <math.h>

#define B_  32
#define L_  64
#define D_  768
#define LL_ (L_*L_)     // 4096
#define OUTD_ (2*D_)    // 1536

#define ROWS_PER_BLK 12     // 128 blocks * 12 = 1536 output rows

// scratch
__device__ float g_pooled[B_ * D_];
__device__ float g_ca[B_ * L_];   // coefficient for a1 row r (0 if unused)
__device__ float g_cb[B_ * L_];   // NEGATED coefficient for a2 row r

// ---------------------------------------------------------------------------
// A1: per-batch t-dots -> masked softmax max/denom -> per-row coefficients
// grid = B_, block = 256 (8 warps)
// ---------------------------------------------------------------------------
__global__ __launch_bounds__(256) void stageA1(
    const float* __restrict__ a1, const float* __restrict__ a2,
    const int*   __restrict__ m1, const int*   __restrict__ m2,
    const float* __restrict__ we_w)
{
    __shared__ float sw[D_];
    __shared__ float t1[L_], t2[L_];
    __shared__ float red[8];
    __shared__ int   sl1, sl2;
    __shared__ float smax, sdenom;

    const int b    = blockIdx.x;
    const int tid  = threadIdx.x;
    const int lane = tid & 31;
    const int wid  = tid >> 5;

    for (int i = tid; i < D_; i += 256) sw[i] = we_w[i];

    if (wid == 0) {
        int s = m1[b*L_ + lane] + m1[b*L_ + lane + 32];
        #pragma unroll
        for (int o = 16; o; o >>= 1) s += __shfl_xor_sync(0xffffffffu, s, o);
        if (lane == 0) sl1 = s - 2;
    } else if (wid == 1) {
        int s = m2[b*L_ + lane] + m2[b*L_ + lane + 32];
        #pragma unroll
        for (int o = 16; o; o >>= 1) s += __shfl_xor_sync(0xffffffffu, s, o);
        if (lane == 0) sl2 = s - 2;
    }
    __syncthreads();

    const float4* base1v = (const float4*)(a1 + (size_t)b * L_ * D_);
    const float4* base2v = (const float4*)(a2 + (size_t)b * L_ * D_);
    const float4* swv    = (const float4*)sw;

    // t-dots: 128 row-tasks over 8 warps, lanes over D
    for (int task = wid; task < 2*L_; task += 8) {
        const float4* row = (task < L_) ? (base1v + task*(D_/4))
                                        : (base2v + (task - L_)*(D_/4));
        float s = 0.f;
        #pragma unroll
        for (int k = 0; k < 6; k++) {
            float4 v = row[lane + 32*k];
            float4 w = swv[lane + 32*k];
            s += v.x*w.x + v.y*w.y + v.z*w.z + v.w*w.w;
        }
        #pragma unroll
        for (int o = 16; o; o >>= 1) s += __shfl_xor_sync(0xffffffffu, s, o);
        if (lane == 0) { if (task < L_) t1[task] = s; else t2[task - L_] = s; }
    }
    __syncthreads();

    const int l1 = sl1, l2 = sl2;
    const int nvalid = l1 * l2;

    // pass 1: max over 4096 masked logits
    float lmax = -1e30f;
    for (int kk = tid; kk < LL_; kk += 256) {
        float we = 0.f;
        if (kk < nvalid) {
            int i = kk / l2;
            int j = kk - i*l2;
            we = t1[i+1] - t2[j+1];
        }
        float m = (fabsf(we) < 1e-7f) ? -1e7f : we;
        lmax = fmaxf(lmax, m);
    }
    #pragma unroll
    for (int o = 16; o; o >>= 1) lmax = fmaxf(lmax, __shfl_xor_sync(0xffffffffu, lmax, o));
    if (lane == 0) red[wid] = lmax;
    __syncthreads();
    if (tid == 0) {
        float m = red[0];
        #pragma unroll
        for (int i = 1; i < 8; i++) m = fmaxf(m, red[i]);
        smax = m;
    }
    __syncthreads();
    const float mx = smax;

    // pass 2: denominator
    float lsum = 0.f;
    for (int kk = tid; kk < LL_; kk += 256) {
        float we = 0.f;
        if (kk < nvalid) {
            int i = kk / l2;
            int j = kk - i*l2;
            we = t1[i+1] - t2[j+1];
        }
        float m = (fabsf(we) < 1e-7f) ? -1e7f : we;
        lsum += __expf(m - mx);
    }
    #pragma unroll
    for (int o = 16; o; o >>= 1) lsum += __shfl_xor_sync(0xffffffffu, lsum, o);
    if (lane == 0) red[wid] = lsum;
    __syncthreads();
    if (tid == 0) {
        float s = 0.f;
        #pragma unroll
        for (int i = 0; i < 8; i++) s += red[i];
        sdenom = s;
    }
    __syncthreads();
    const float inv_denom = 1.f / sdenom;

    // pass 3: marginals, warp-per-row, lanes parallel over the inner index
    for (int task = wid; task < 2*L_; task += 8) {
        if (task < L_) {
            const int i = task;
            float s = 0.f;
            if (i < l1) {
                const float ti = t1[i+1];
                #pragma unroll
                for (int base = 0; base < L_; base += 32) {
                    int jj = base + lane;
                    if (jj < l2) {
                        float we = ti - t2[jj+1];
                        float m = (fabsf(we) < 1e-7f) ? -1e7f : we;
                        s += __expf(m - mx);
                    }
                }
            }
            #pragma unroll
            for (int o = 16; o; o >>= 1) s += __shfl_xor_sync(0xffffffffu, s, o);
            if (lane == 0 && i + 1 < L_) g_ca[b*L_ + i + 1] = s * inv_denom;
        } else {
            const int j = task - L_;
            float s = 0.f;
            if (j < l2) {
                const float tj = t2[j+1];
                #pragma unroll
                for (int base = 0; base < L_; base += 32) {
                    int ii = base + lane;
                    if (ii < l1) {
                        float we = t1[ii+1] - tj;
                        float m = (fabsf(we) < 1e-7f) ? -1e7f : we;
                        s += __expf(m - mx);
                    }
                }
            }
            #pragma unroll
            for (int o = 16; o; o >>= 1) s += __shfl_xor_sync(0xffffffffu, s, o);
            if (lane == 0 && j + 1 < L_) g_cb[b*L_ + j + 1] = -s * inv_denom;
        }
    }
    if (tid == 0) { g_ca[b*L_] = 0.f; g_cb[b*L_] = 0.f; }
}

// ---------------------------------------------------------------------------
// A2: pooled[b,:] = sum_r ca[r]*a1[b,r,:] + cb[r]*a2[b,r,:]
// grid = (6, B_), block = 256. Block owns one batch + 32 float4 columns.
// Thread: float4 column = lane, row-group = wid (8 rows each per tensor).
// ---------------------------------------------------------------------------
__global__ __launch_bounds__(256) void stageA2(
    const float* __restrict__ a1, const float* __restrict__ a2)
{
    __shared__ float4 part[8][32];

    const int b    = blockIdx.y;
    const int cc   = blockIdx.x;           // column chunk (0..5)
    const int lane = threadIdx.x & 31;
    const int rg   = threadIdx.x >> 5;     // row group (0..7)
    const int col  = cc*32 + lane;         // float4 column (0..191)

    const float4* base1v = (const float4*)(a1 + (size_t)b * L_ * D_);
    const float4* base2v = (const float4*)(a2 + (size_t)b * L_ * D_);
    const float*  ca = g_ca + b*L_;
    const float*  cb = g_cb + b*L_;

    float4 acc = make_float4(0.f, 0.f, 0.f, 0.f);
    #pragma unroll
    for (int k = 0; k < 8; k++) {
        const int r = rg + 8*k;
        const float c1 = ca[r];
        const float c2 = cb[r];
        float4 v1 = base1v[r*(D_/4) + col];
        float4 v2 = base2v[r*(D_/4) + col];
        acc.x += c1*v1.x + c2*v2.x;
        acc.y += c1*v1.y + c2*v2.y;
        acc.z += c1*v1.z + c2*v2.z;
        acc.w += c1*v1.w + c2*v2.w;
    }
    part[rg][lane] = acc;
    __syncthreads();

    if (threadIdx.x < 32) {
        float4 s = part[0][lane];
        #pragma unroll
        for (int k = 1; k < 8; k++) {
            float4 v = part[k][lane];
            s.x += v.x; s.y += v.y; s.z += v.z; s.w += v.w;
        }
        ((float4*)g_pooled)[b*(D_/4) + col] = s;
    }
}

// ---------------------------------------------------------------------------
// Stage B: out[b,o] = tanh( dot(pooled[b], fc_w[o]) + fc_b[o] )
// grid = 128 x 512 threads (16 warps). Warp owns 2 batches, sweeps 12 rows
// from the smem-staged fc_w tile.
// ---------------------------------------------------------------------------
__global__ __launch_bounds__(512) void stageB(
    const float* __restrict__ fc_w, const float* __restrict__ fc_b,
    float* __restrict__ out)
{
    __shared__ float sA[ROWS_PER_BLK * D_];   // 36 KB

    const int tid  = threadIdx.x;
    const int lane = tid & 31;
    const int wid  = tid >> 5;                // 0..15
    const int o0   = blockIdx.x * ROWS_PER_BLK;
    const int b0   = wid * 2;                 // 16 warps x 2 batches = 32

    // stage fc_w tile: 2304 float4 over 512 threads
    {
        const float4* src = (const float4*)(fc_w + (size_t)o0 * D_);
        float4*       dst = (float4*)sA;
        for (int idx = tid; idx < ROWS_PER_BLK * D_ / 4; idx += 512)
            dst[idx] = src[idx];
    }

    // preload pooled for 2 batches
    const float4* poolv = (const float4*)g_pooled;
    float4 p[2][6];
    #pragma unroll
    for (int bb = 0; bb < 2; bb++)
        #pragma unroll
        for (int k = 0; k < 6; k++)
            p[bb][k] = poolv[(b0 + bb)*(D_/4) + lane + 32*k];

    __syncthreads();

    const float4* sAv = (const float4*)sA;

    #pragma unroll
    for (int r = 0; r < ROWS_PER_BLK; r++) {
        const int o = o0 + r;
        float a0 = 0.f, a1 = 0.f;
        #pragma unroll
        for (int k = 0; k < 6; k++) {
            float4 w = sAv[r*(D_/4) + lane + 32*k];
            a0 += w.x*p[0][k].x + w.y*p[0][k].y + w.z*p[0][k].z + w.w*p[0][k].w;
            a1 += w.x*p[1][k].x + w.y*p[1][k].y + w.z*p[1][k].z + w.w*p[1][k].w;
        }
        #pragma unroll
        for (int off = 16; off; off >>= 1) {
            a0 += __shfl_xor_sync(0xffffffffu, a0, off);
            a1 += __shfl_xor_sync(0xffffffffu, a1, off);
        }
        if (lane == 0) {
            const float bias = fc_b[o];
            out[(size_t)(b0+0)*OUTD_ + o] = tanhf(a0 + bias);
            out[(size_t)(b0+1)*OUTD_ + o] = tanhf(a1 + bias);
        }
    }
}

extern "C" void kernel_launch(void* const* d_in, const int* in_sizes, int n_in,
                              void* d_out, int out_size)
{
    const float* a1   = (const float*)d_in[0];  // (B, L, D)
    const float* a2   = (const float*)d_in[1];  // (B, L, D)
    const int*   m1   = (const int*)  d_in[2];  // (B, L)
    const int*   m2   = (const int*)  d_in[3];  // (B, L)
    const float* we_w = (const float*)d_in[4];  // (1, D)
    const float* fc_w = (const float*)d_in[5];  // (2D, D)
    const float* fc_b = (const float*)d_in[6];  // (2D,)
    float* out = (float*)d_out;                 // (B, 2D)

    stageA1<<<B_, 256>>>(a1, a2, m1, m2, we_w);
    stageA2<<<dim3(6, B_), 256>>>(a1, a2);
    stageB<<<OUTD_ / ROWS_PER_BLK, 512>>>(fc_w, fc_b, out);
}

// round 4
// speedup vs baseline: 2.0663x; 1.5345x over previous
#include <cuda_runtime.h>
#include <math.h>

#define B_  32
#define L_  64
#define D_  768
#define LL_ (L_*L_)     // 4096
#define OUTD_ (2*D_)    // 1536

#define ROWS_PER_BLK 4      // stageB: 384 blocks * 4 = 1536 output rows

// scratch
__device__ float g_pooled[B_ * D_];
__device__ float g_t[B_ * 2 * L_];   // t1 (64) then t2 (64) per batch
__device__ float g_ca[B_ * L_];      // coefficient for a1 row r (0 if unused)
__device__ float g_cb[B_ * L_];      // NEGATED coefficient for a2 row r

// ---------------------------------------------------------------------------
// T: t[b, r] = dot(row, we_w) for all 128 rows (64 of a1, 64 of a2) per batch.
// grid = (16, B_), block = 256 (8 warps). Warp owns one row. 512 blocks total.
// ---------------------------------------------------------------------------
__global__ __launch_bounds__(256) void stageT(
    const float* __restrict__ a1, const float* __restrict__ a2,
    const float* __restrict__ we_w)
{
    __shared__ float sw[D_];
    const int b    = blockIdx.y;
    const int lane = threadIdx.x & 31;
    const int wid  = threadIdx.x >> 5;
    const int task = blockIdx.x * 8 + wid;   // 0..127

    for (int i = threadIdx.x; i < D_; i += 256) sw[i] = we_w[i];
    __syncthreads();

    const float4* row = (task < L_)
        ? ((const float4*)(a1 + (size_t)b * L_ * D_) + task * (D_/4))
        : ((const float4*)(a2 + (size_t)b * L_ * D_) + (task - L_) * (D_/4));
    const float4* swv = (const float4*)sw;

    float s = 0.f;
    #pragma unroll
    for (int k = 0; k < 6; k++) {
        float4 v = row[lane + 32*k];
        float4 w = swv[lane + 32*k];
        s += v.x*w.x + v.y*w.y + v.z*w.z + v.w*w.w;
    }
    #pragma unroll
    for (int o = 16; o; o >>= 1) s += __shfl_xor_sync(0xffffffffu, s, o);
    if (lane == 0) g_t[b * 2*L_ + task] = s;
}

// ---------------------------------------------------------------------------
// M: per-batch masked-softmax marginals from t-values. grid = B_, block 256.
// ca[i+1] = rowsum_i / denom ; cb[j+1] = -colsum_j / denom ; others 0.
// denom = sum(rowsums) + (LL - l1*l2) * exp(-1e7 - mx)
// ---------------------------------------------------------------------------
__global__ __launch_bounds__(256) void stageM(
    const int* __restrict__ m1, const int* __restrict__ m2)
{
    __shared__ float t1[L_], t2[L_];
    __shared__ float rows[L_], cols[L_];
    __shared__ float red[8];
    __shared__ int   sl1, sl2;
    __shared__ float smax, sinvd;

    const int b    = blockIdx.x;
    const int tid  = threadIdx.x;
    const int lane = tid & 31;
    const int wid  = tid >> 5;

    if (tid < 2*L_) {
        float v = g_t[b*2*L_ + tid];
        if (tid < L_) t1[tid] = v; else t2[tid - L_] = v;
    }
    if (tid < 2*L_) { rows[tid & (L_-1)] = 0.f; }   // rows+cols zeroed below
    if (tid < L_) { rows[tid] = 0.f; cols[tid] = 0.f; }

    if (wid == 0) {
        int s = m1[b*L_ + lane] + m1[b*L_ + lane + 32];
        #pragma unroll
        for (int o = 16; o; o >>= 1) s += __shfl_xor_sync(0xffffffffu, s, o);
        if (lane == 0) sl1 = s - 2;
    } else if (wid == 1) {
        int s = m2[b*L_ + lane] + m2[b*L_ + lane + 32];
        #pragma unroll
        for (int o = 16; o; o >>= 1) s += __shfl_xor_sync(0xffffffffu, s, o);
        if (lane == 0) sl2 = s - 2;
    }
    __syncthreads();

    const int l1 = sl1, l2 = sl2;

    // --- max over valid masked logits; -1e7 floor always present (padding) ---
    float lmax = -1e7f;
    for (int i = wid; i < l1; i += 8) {
        const float ti = t1[i+1];
        #pragma unroll
        for (int base = 0; base < L_; base += 32) {
            int j = base + lane;
            if (j < l2) {
                float we = ti - t2[j+1];
                float m = (fabsf(we) < 1e-7f) ? -1e7f : we;
                lmax = fmaxf(lmax, m);
            }
        }
    }
    #pragma unroll
    for (int o = 16; o; o >>= 1) lmax = fmaxf(lmax, __shfl_xor_sync(0xffffffffu, lmax, o));
    if (lane == 0) red[wid] = lmax;
    __syncthreads();
    if (tid == 0) {
        float m = red[0];
        #pragma unroll
        for (int i = 1; i < 8; i++) m = fmaxf(m, red[i]);
        smax = m;
    }
    __syncthreads();
    const float mx = smax;

    // --- row sums ---
    for (int i = wid; i < l1; i += 8) {
        const float ti = t1[i+1];
        float s = 0.f;
        #pragma unroll
        for (int base = 0; base < L_; base += 32) {
            int j = base + lane;
            if (j < l2) {
                float we = ti - t2[j+1];
                float m = (fabsf(we) < 1e-7f) ? -1e7f : we;
                s += __expf(m - mx);
            }
        }
        #pragma unroll
        for (int o = 16; o; o >>= 1) s += __shfl_xor_sync(0xffffffffu, s, o);
        if (lane == 0) rows[i] = s;
    }
    // --- col sums ---
    for (int j = wid; j < l2; j += 8) {
        const float tj = t2[j+1];
        float s = 0.f;
        #pragma unroll
        for (int base = 0; base < L_; base += 32) {
            int i = base + lane;
            if (i < l1) {
                float we = t1[i+1] - tj;
                float m = (fabsf(we) < 1e-7f) ? -1e7f : we;
                s += __expf(m - mx);
            }
        }
        #pragma unroll
        for (int o = 16; o; o >>= 1) s += __shfl_xor_sync(0xffffffffu, s, o);
        if (lane == 0) cols[j] = s;
    }
    __syncthreads();

    // --- denom from rowsums + padding correction ---
    if (wid == 0) {
        float s = rows[lane] + rows[lane + 32];
        #pragma unroll
        for (int o = 16; o; o >>= 1) s += __shfl_xor_sync(0xffffffffu, s, o);
        if (lane == 0) {
            float pad = (float)(LL_ - l1*l2) * __expf(-1e7f - mx);
            sinvd = 1.f / (s + pad);
        }
    }
    __syncthreads();
    const float invd = sinvd;

    // --- write coefficients (full 64-entry vectors, zeros where unused) ---
    if (tid < L_) {
        float v = (tid >= 1 && tid - 1 < l1) ? rows[tid-1] * invd : 0.f;
        g_ca[b*L_ + tid] = v;
    } else if (tid < 2*L_) {
        int j = tid - L_;
        float v = (j >= 1 && j - 1 < l2) ? -cols[j-1] * invd : 0.f;
        g_cb[b*L_ + j] = v;
    }
}

// ---------------------------------------------------------------------------
// A2: pooled[b,:] = sum_r ca[r]*a1[b,r,:] + cb[r]*a2[b,r,:]
// grid = (6, B_), block = 256. Thread: float4 col = lane, row-group = wid.
// ---------------------------------------------------------------------------
__global__ __launch_bounds__(256) void stageA2(
    const float* __restrict__ a1, const float* __restrict__ a2)
{
    __shared__ float4 part[8][32];

    const int b    = blockIdx.y;
    const int cc   = blockIdx.x;
    const int lane = threadIdx.x & 31;
    const int rg   = threadIdx.x >> 5;
    const int col  = cc*32 + lane;

    const float4* base1v = (const float4*)(a1 + (size_t)b * L_ * D_);
    const float4* base2v = (const float4*)(a2 + (size_t)b * L_ * D_);
    const float*  ca = g_ca + b*L_;
    const float*  cb = g_cb + b*L_;

    float4 acc = make_float4(0.f, 0.f, 0.f, 0.f);
    #pragma unroll
    for (int k = 0; k < 8; k++) {
        const int r = rg + 8*k;
        const float c1 = ca[r];
        const float c2 = cb[r];
        float4 v1 = base1v[r*(D_/4) + col];
        float4 v2 = base2v[r*(D_/4) + col];
        acc.x += c1*v1.x + c2*v2.x;
        acc.y += c1*v1.y + c2*v2.y;
        acc.z += c1*v1.z + c2*v2.z;
        acc.w += c1*v1.w + c2*v2.w;
    }
    part[rg][lane] = acc;
    __syncthreads();

    if (threadIdx.x < 32) {
        float4 s = part[0][lane];
        #pragma unroll
        for (int k = 1; k < 8; k++) {
            float4 v = part[k][lane];
            s.x += v.x; s.y += v.y; s.z += v.z; s.w += v.w;
        }
        ((float4*)g_pooled)[b*(D_/4) + col] = s;
    }
}

// ---------------------------------------------------------------------------
// B: out[b,o] = tanh( dot(pooled[b], fc_w[o]) + fc_b[o] )
// grid = 384 x 256 threads (8 warps, 4 batches/warp, 4 rows/block).
// fc_w tile (4x768 = 12KB) staged to smem; pooled in registers.
// ---------------------------------------------------------------------------
__global__ __launch_bounds__(256) void stageB(
    const float* __restrict__ fc_w, const float* __restrict__ fc_b,
    float* __restrict__ out)
{
    __shared__ float sA[ROWS_PER_BLK * D_];   // 12 KB

    const int tid  = threadIdx.x;
    const int lane = tid & 31;
    const int wid  = tid >> 5;
    const int o0   = blockIdx.x * ROWS_PER_BLK;
    const int b0   = wid * 4;                 // 8 warps x 4 batches = 32

    // stage fc_w tile: 768 float4 / 256 threads = 3 each, independent
    {
        const float4* src = (const float4*)(fc_w + (size_t)o0 * D_);
        float4*       dst = (float4*)sA;
        #pragma unroll
        for (int k = 0; k < 3; k++)
            dst[tid + 256*k] = src[tid + 256*k];
    }

    // preload pooled for 4 batches
    const float4* poolv = (const float4*)g_pooled;
    float4 p[4][6];
    #pragma unroll
    for (int bb = 0; bb < 4; bb++)
        #pragma unroll
        for (int k = 0; k < 6; k++)
            p[bb][k] = poolv[(b0 + bb)*(D_/4) + lane + 32*k];

    __syncthreads();

    const float4* sAv = (const float4*)sA;

    #pragma unroll
    for (int r = 0; r < ROWS_PER_BLK; r++) {
        const int o = o0 + r;
        float a0 = 0.f, a1 = 0.f, a2 = 0.f, a3 = 0.f;
        #pragma unroll
        for (int k = 0; k < 6; k++) {
            float4 w = sAv[r*(D_/4) + lane + 32*k];
            a0 += w.x*p[0][k].x + w.y*p[0][k].y + w.z*p[0][k].z + w.w*p[0][k].w;
            a1 += w.x*p[1][k].x + w.y*p[1][k].y + w.z*p[1][k].z + w.w*p[1][k].w;
            a2 += w.x*p[2][k].x + w.y*p[2][k].y + w.z*p[2][k].z + w.w*p[2][k].w;
            a3 += w.x*p[3][k].x + w.y*p[3][k].y + w.z*p[3][k].z + w.w*p[3][k].w;
        }
        #pragma unroll
        for (int off = 16; off; off >>= 1) {
            a0 += __shfl_xor_sync(0xffffffffu, a0, off);
            a1 += __shfl_xor_sync(0xffffffffu, a1, off);
            a2 += __shfl_xor_sync(0xffffffffu, a2, off);
            a3 += __shfl_xor_sync(0xffffffffu, a3, off);
        }
        if (lane == 0) {
            const float bias = fc_b[o];
            out[(size_t)(b0+0)*OUTD_ + o] = tanhf(a0 + bias);
            out[(size_t)(b0+1)*OUTD_ + o] = tanhf(a1 + bias);
            out[(size_t)(b0+2)*OUTD_ + o] = tanhf(a2 + bias);
            out[(size_t)(b0+3)*OUTD_ + o] = tanhf(a3 + bias);
        }
    }
}

extern "C" void kernel_launch(void* const* d_in, const int* in_sizes, int n_in,
                              void* d_out, int out_size)
{
    const float* a1   = (const float*)d_in[0];  // (B, L, D)
    const float* a2   = (const float*)d_in[1];  // (B, L, D)
    const int*   m1   = (const int*)  d_in[2];  // (B, L)
    const int*   m2   = (const int*)  d_in[3];  // (B, L)
    const float* we_w = (const float*)d_in[4];  // (1, D)
    const float* fc_w = (const float*)d_in[5];  // (2D, D)
    const float* fc_b = (const float*)d_in[6];  // (2D,)
    float* out = (float*)d_out;                 // (B, 2D)

    stageT<<<dim3(16, B_), 256>>>(a1, a2, we_w);
    stageM<<<B_, 256>>>(m1, m2);
    stageA2<<<dim3(6, B_), 256>>>(a1, a2);
    stageB<<<OUTD_ / ROWS_PER_BLK, 256>>>(fc_w, fc_b, out);
}